// round 7
// baseline (speedup 1.0000x reference)
#include <cuda_runtime.h>
#include <cuda_bf16.h>
#include <math.h>

// ---------------------------------------------------------------------------
// Problem constants
// ---------------------------------------------------------------------------
#define BSZ   16
#define CCH   2048
#define HW    128
#define C8    256
#define NV    16
#define VV    128
#define GNUM  2

// ------------------------- scratch (device globals) ------------------------
__device__ __align__(256) float d_q   [BSZ * C8 * HW];
__device__ __align__(256) float d_k   [BSZ * C8 * HW];
__device__ __align__(256) float d_v   [BSZ * CCH * HW];
__device__ __align__(256) float d_att1[BSZ * HW * HW];
__device__ __align__(256) float d_y1  [BSZ * CCH * HW];
__device__ __align__(256) float d_h   [NV * VV * CCH];
__device__ __align__(256) float d_ip  [NV * VV * VV];
__device__ __align__(256) float d_graph[NV * VV * VV];
__device__ __align__(256) float d_hp  [NV * VV * CCH];
__device__ __align__(256) float d_gbuf[NV * VV * CCH];
__device__ __align__(256) float d_mean[CCH];
__device__ __align__(256) float d_var [CCH];

// ---------------------- shared mma/ldsm/split helpers -----------------------
__device__ __forceinline__ void ldsm4(unsigned* r, unsigned addr) {
    asm volatile("ldmatrix.sync.aligned.m8n8.x4.shared.b16 {%0,%1,%2,%3}, [%4];"
        : "=r"(r[0]), "=r"(r[1]), "=r"(r[2]), "=r"(r[3]) : "r"(addr));
}
__device__ __forceinline__ void ldsm4t(unsigned* r, unsigned addr) {
    asm volatile("ldmatrix.sync.aligned.m8n8.x4.trans.shared.b16 {%0,%1,%2,%3}, [%4];"
        : "=r"(r[0]), "=r"(r[1]), "=r"(r[2]), "=r"(r[3]) : "r"(addr));
}
__device__ __forceinline__ void mma16816(float* c, const unsigned* a, const unsigned* b) {
    asm volatile("mma.sync.aligned.m16n8k16.row.col.f32.bf16.bf16.f32 "
        "{%0,%1,%2,%3}, {%4,%5,%6,%7}, {%8,%9}, {%0,%1,%2,%3};"
        : "+f"(c[0]), "+f"(c[1]), "+f"(c[2]), "+f"(c[3])
        : "r"(a[0]), "r"(a[1]), "r"(a[2]), "r"(a[3]), "r"(b[0]), "r"(b[1]));
}
__device__ __forceinline__ void bsplit(float x, __nv_bfloat16& h, __nv_bfloat16& l) {
    h = __float2bfloat16(x);
    l = __float2bfloat16(x - __bfloat162float(h));
}
__device__ __forceinline__ unsigned packbf(float a, float b) {
    __nv_bfloat162 p; p.x = __float2bfloat16(a); p.y = __float2bfloat16(b);
    return *(unsigned*)&p;
}
__device__ __forceinline__ unsigned packlo(float a, float b, unsigned hipack) {
    __nv_bfloat162 h = *(__nv_bfloat162*)&hipack;
    return packbf(a - __bfloat162float(h.x), b - __bfloat162float(h.y));
}

// ======================= bf16-split tensor-core GEMM ========================
// 512 threads, 16 warps, warp tile 16x64. Block 128x128, K-step 32,
// double-buffered smem. acc = AhBh + AhBl + AlBh.
#define TST   40
#define TTILE (128 * TST)
#define TSMEM (2 * 4 * TTILE * 2)

template<int TA, int TB>
__global__ __launch_bounds__(512)
void tgemm_kernel(const float* __restrict__ Ag, const float* __restrict__ Bg,
                  float* __restrict__ Cg,
                  int M, int N, int K,
                  long sA, long sB, long sC,
                  const float* __restrict__ bias,
                  const float* __restrict__ Res, long sRes,
                  float alphaH, const float* __restrict__ alphaD)
{
    extern __shared__ __align__(16) __nv_bfloat16 ts[];

    const int bz = blockIdx.z;
    const float* A = Ag + (long)bz * sA;
    const float* B = Bg + (long)bz * sB;
    float*       C = Cg + (long)bz * sC;

    const int m0 = blockIdx.y * 128;
    const int n0 = blockIdx.x * 128;
    const int tid  = threadIdx.x;
    const int wid  = tid >> 5;           // 0..15
    const int lane = tid & 31;
    const int warp_m = (wid >> 1) * 16;  // 0..112
    const int warp_n = (wid & 1) * 64;
    const int mi = lane >> 3, ri = lane & 7;
    const int g  = lane >> 2, t  = lane & 3;

    const unsigned sbase = (unsigned)__cvta_generic_to_shared(ts);

    const unsigned aoff =
        ((warp_m + ((mi & 1) << 3) + ri) * TST + ((mi >> 1) << 3)) * 2;
    unsigned boff[4];
#pragma unroll
    for (int fp = 0; fp < 4; fp++)
        boff[fp] = ((warp_n + fp * 16 + ((mi >> 1) << 3) + ri) * TST + ((mi & 1) << 3)) * 2;

    float acc[8][4];
#pragma unroll
    for (int j = 0; j < 8; j++)
#pragma unroll
        for (int q = 0; q < 4; q++) acc[j][q] = 0.f;

    float4 pa[2], pb[2];
    const int rA = tid >> 2, cA = (tid & 3) * 8;     // direct path
    const int kA = tid >> 4, mA = (tid & 15) * 8;    // transpose path

#define LOADG(k0)                                                              \
    do {                                                                       \
        if (TA == 0) {                                                         \
            pa[0] = *(const float4*)&A[(long)(m0 + rA) * K + (k0) + cA];       \
            pa[1] = *(const float4*)&A[(long)(m0 + rA) * K + (k0) + cA + 4];   \
        } else {                                                               \
            pa[0] = *(const float4*)&A[(long)((k0) + kA) * M + m0 + mA];       \
            pa[1] = *(const float4*)&A[(long)((k0) + kA) * M + m0 + mA + 4];   \
        }                                                                      \
        if (TB == 1) {                                                         \
            pb[0] = *(const float4*)&B[(long)(n0 + rA) * K + (k0) + cA];       \
            pb[1] = *(const float4*)&B[(long)(n0 + rA) * K + (k0) + cA + 4];   \
        } else {                                                               \
            pb[0] = *(const float4*)&B[(long)((k0) + kA) * N + n0 + mA];       \
            pb[1] = *(const float4*)&B[(long)((k0) + kA) * N + n0 + mA + 4];   \
        }                                                                      \
    } while (0)

#define CVSTORE(bf)                                                            \
    do {                                                                       \
        __nv_bfloat16* Ah = ts + ((bf) * 4 + 0) * TTILE;                       \
        __nv_bfloat16* Al = ts + ((bf) * 4 + 1) * TTILE;                       \
        __nv_bfloat16* Bh = ts + ((bf) * 4 + 2) * TTILE;                       \
        __nv_bfloat16* Bl = ts + ((bf) * 4 + 3) * TTILE;                       \
        float va[8] = { pa[0].x, pa[0].y, pa[0].z, pa[0].w,                    \
                        pa[1].x, pa[1].y, pa[1].z, pa[1].w };                  \
        __nv_bfloat16 h[8], l[8];                                              \
        _Pragma("unroll")                                                      \
        for (int i = 0; i < 8; i++) bsplit(va[i], h[i], l[i]);                 \
        if (TA == 0) {                                                         \
            int base = rA * TST + cA;                                          \
            _Pragma("unroll")                                                  \
            for (int i = 0; i < 4; i++) {                                      \
                __nv_bfloat162 hh; hh.x = h[2*i]; hh.y = h[2*i+1];             \
                __nv_bfloat162 ll; ll.x = l[2*i]; ll.y = l[2*i+1];             \
                *(__nv_bfloat162*)(Ah + base + 2*i) = hh;                      \
                *(__nv_bfloat162*)(Al + base + 2*i) = ll;                      \
            }                                                                  \
        } else {                                                               \
            _Pragma("unroll")                                                  \
            for (int i = 0; i < 8; i++) {                                      \
                Ah[(mA + i) * TST + kA] = h[i];                                \
                Al[(mA + i) * TST + kA] = l[i];                                \
            }                                                                  \
        }                                                                      \
        float vb[8] = { pb[0].x, pb[0].y, pb[0].z, pb[0].w,                    \
                        pb[1].x, pb[1].y, pb[1].z, pb[1].w };                  \
        _Pragma("unroll")                                                      \
        for (int i = 0; i < 8; i++) bsplit(vb[i], h[i], l[i]);                 \
        if (TB == 1) {                                                         \
            int base = rA * TST + cA;                                          \
            _Pragma("unroll")                                                  \
            for (int i = 0; i < 4; i++) {                                      \
                __nv_bfloat162 hh; hh.x = h[2*i]; hh.y = h[2*i+1];             \
                __nv_bfloat162 ll; ll.x = l[2*i]; ll.y = l[2*i+1];             \
                *(__nv_bfloat162*)(Bh + base + 2*i) = hh;                      \
                *(__nv_bfloat162*)(Bl + base + 2*i) = ll;                      \
            }                                                                  \
        } else {                                                               \
            _Pragma("unroll")                                                  \
            for (int i = 0; i < 8; i++) {                                      \
                Bh[(mA + i) * TST + kA] = h[i];                                \
                Bl[(mA + i) * TST + kA] = l[i];                                \
            }                                                                  \
        }                                                                      \
    } while (0)

#define MMASTEP(bf)                                                            \
    do {                                                                       \
        const unsigned bAh = sbase + ((bf) * 4 + 0) * TTILE * 2;               \
        const unsigned bAl = sbase + ((bf) * 4 + 1) * TTILE * 2;               \
        const unsigned bBh = sbase + ((bf) * 4 + 2) * TTILE * 2;               \
        const unsigned bBl = sbase + ((bf) * 4 + 3) * TTILE * 2;               \
        _Pragma("unroll")                                                      \
        for (int kk = 0; kk < 2; kk++) {                                       \
            unsigned ah[4], al[4], bh[4][4], bl[4][4];                         \
            ldsm4(ah, bAh + aoff + kk * 32);                                   \
            ldsm4(al, bAl + aoff + kk * 32);                                   \
            _Pragma("unroll")                                                  \
            for (int fp = 0; fp < 4; fp++) {                                   \
                ldsm4(bh[fp], bBh + boff[fp] + kk * 32);                       \
                ldsm4(bl[fp], bBl + boff[fp] + kk * 32);                       \
            }                                                                  \
            _Pragma("unroll")                                                  \
            for (int fp = 0; fp < 4; fp++)                                     \
                _Pragma("unroll")                                              \
                for (int hh = 0; hh < 2; hh++) {                               \
                    float* c = acc[fp * 2 + hh];                               \
                    mma16816(c, ah, &bh[fp][2 * hh]);                          \
                    mma16816(c, ah, &bl[fp][2 * hh]);                          \
                    mma16816(c, al, &bh[fp][2 * hh]);                          \
                }                                                              \
        }                                                                      \
    } while (0)

    LOADG(0);
    CVSTORE(0);
    __syncthreads();

    const int nt = K / 32;
    for (int tI = 0; tI < nt; tI++) {
        if (tI + 1 < nt) LOADG((tI + 1) * 32);
        MMASTEP(tI & 1);
        if (tI + 1 < nt) {
            CVSTORE((tI + 1) & 1);
            __syncthreads();
        }
    }

    const float alpha = alphaD ? *alphaD : alphaH;
    const int m = m0 + warp_m + g;
    const float bi0 = bias ? __ldg(&bias[m])     : 0.f;
    const float bi1 = bias ? __ldg(&bias[m + 8]) : 0.f;
#pragma unroll
    for (int fj = 0; fj < 8; fj++) {
        const int n = n0 + warp_n + fj * 8 + t * 2;
        const float* c = acc[fj];
        const long off0 = (long)m * N + n;
        const long off1 = (long)(m + 8) * N + n;
        float2 o0, o1;
        o0.x = alpha * c[0] + bi0; o0.y = alpha * c[1] + bi0;
        o1.x = alpha * c[2] + bi1; o1.y = alpha * c[3] + bi1;
        if (Res) {
            float2 r0 = *(const float2*)&Res[(long)bz * sRes + off0];
            float2 r1 = *(const float2*)&Res[(long)bz * sRes + off1];
            o0.x += r0.x; o0.y += r0.y;
            o1.x += r1.x; o1.y += r1.y;
        }
        *(float2*)&C[off0] = o0;
        *(float2*)&C[off1] = o1;
    }
#undef LOADG
#undef CVSTORE
#undef MMASTEP
}

// --------------------------- reductions ------------------------------------
__device__ __forceinline__ float warpMax(float v) {
#pragma unroll
    for (int o = 16; o; o >>= 1) v = fmaxf(v, __shfl_xor_sync(0xffffffffu, v, o));
    return v;
}
__device__ __forceinline__ float warpSum(float v) {
#pragma unroll
    for (int o = 16; o; o >>= 1) v += __shfl_xor_sync(0xffffffffu, v, o);
    return v;
}

// in-place row softmax; one block per row
__global__ void softmax_kernel(float* __restrict__ d, int ncols)
{
    __shared__ float red[32];
    __shared__ float bcast;
    const long row = blockIdx.x;
    float* p = d + row * (long)ncols;
    const int tid = threadIdx.x, nt = blockDim.x;

    float m = -1e30f;
    for (int i = tid; i < ncols; i += nt) m = fmaxf(m, p[i]);
    m = warpMax(m);
    if ((tid & 31) == 0) red[tid >> 5] = m;
    __syncthreads();
    if (tid < 32) {
        float v = (tid < (nt >> 5)) ? red[tid] : -1e30f;
        v = warpMax(v);
        if (tid == 0) bcast = v;
    }
    __syncthreads();
    m = bcast;

    float s = 0.f;
    for (int i = tid; i < ncols; i += nt) {
        float e = __expf(p[i] - m);
        p[i] = e;
        s += e;
    }
    __syncthreads();
    s = warpSum(s);
    if ((tid & 31) == 0) red[tid >> 5] = s;
    __syncthreads();
    if (tid < 32) {
        float v = (tid < (nt >> 5)) ? red[tid] : 0.f;
        v = warpSum(v);
        if (tid == 0) bcast = v;
    }
    __syncthreads();
    const float inv = 1.f / bcast;
    for (int i = tid; i < ncols; i += nt) p[i] *= inv;
}

// ================= tensor-core fused CAM (flash style) ======================
#define CST   136
#define CTILE (128 * CST)
#define CAM_SMEM (4 * CTILE * 2)

__global__ __launch_bounds__(256)
void cam_tc_kernel(const float* __restrict__ y1g,
                   const float* __restrict__ gptr,
                   float* __restrict__ outg)
{
    extern __shared__ __align__(16) __nv_bfloat16 cs[];
    __nv_bfloat16* Qh = cs;
    __nv_bfloat16* Ql = cs + CTILE;
    __nv_bfloat16* Kh = cs + 2 * CTILE;
    __nv_bfloat16* Kl = cs + 3 * CTILE;

    const int b  = blockIdx.y;
    const int c0 = blockIdx.x * 128;
    const float* Y = y1g + (long)b * CCH * HW;

    const int tid = threadIdx.x, wid = tid >> 5, lane = tid & 31;
    const int mi = lane >> 3, ri = lane & 7, g = lane >> 2, t = lane & 3;

    const unsigned sb  = (unsigned)__cvta_generic_to_shared(cs);
    const unsigned bQh = sb;
    const unsigned bQl = sb + CTILE * 2;
    const unsigned bKh = sb + 2 * CTILE * 2;
    const unsigned bKl = sb + 3 * CTILE * 2;

    const unsigned aoff = ((wid * 16 + ((mi & 1) << 3) + ri) * CST + ((mi >> 1) << 3)) * 2;
    const unsigned bS = ((((mi >> 1) << 3) + ri) * CST + ((mi & 1) << 3)) * 2;
    const unsigned bT = ((((mi & 1) << 3) + ri) * CST + ((mi >> 1) << 3)) * 2;

    for (int idx = tid; idx < 128 * 32; idx += 256) {
        int r = idx >> 5, hw = (idx & 31) * 4;
        float4 v = *(const float4*)&Y[(long)(c0 + r) * HW + hw];
        __nv_bfloat16 h0,l0,h1,l1,h2,l2,h3,l3;
        bsplit(v.x,h0,l0); bsplit(v.y,h1,l1); bsplit(v.z,h2,l2); bsplit(v.w,h3,l3);
        __nv_bfloat162 a; __nv_bfloat162 c;
        __nv_bfloat162* ph = (__nv_bfloat162*)(Qh + r * CST + hw);
        __nv_bfloat162* pl = (__nv_bfloat162*)(Ql + r * CST + hw);
        a.x = h0; a.y = h1; ph[0] = a;  a.x = h2; a.y = h3; ph[1] = a;
        c.x = l0; c.y = l1; pl[0] = c;  c.x = l2; c.y = l3; pl[1] = c;
    }

    float Sa[16][4], Oa[16][4];
    float m0r = -1e30f, m1r = -1e30f, l0r = 0.f, l1r = 0.f;
#pragma unroll
    for (int j = 0; j < 16; j++) { Oa[j][0]=Oa[j][1]=Oa[j][2]=Oa[j][3]=0.f; }

    for (int tI = 0; tI < 16; tI++) {
        __syncthreads();
        for (int idx = tid; idx < 128 * 32; idx += 256) {
            int d = idx >> 5, hw = (idx & 31) * 4;
            float4 v = *(const float4*)&Y[(long)(tI * 128 + d) * HW + hw];
            __nv_bfloat16 h0,l0,h1,l1,h2,l2,h3,l3;
            bsplit(v.x,h0,l0); bsplit(v.y,h1,l1); bsplit(v.z,h2,l2); bsplit(v.w,h3,l3);
            __nv_bfloat162 a; __nv_bfloat162 c;
            __nv_bfloat162* ph = (__nv_bfloat162*)(Kh + d * CST + hw);
            __nv_bfloat162* pl = (__nv_bfloat162*)(Kl + d * CST + hw);
            a.x = h0; a.y = h1; ph[0] = a;  a.x = h2; a.y = h3; ph[1] = a;
            c.x = l0; c.y = l1; pl[0] = c;  c.x = l2; c.y = l3; pl[1] = c;
        }
        __syncthreads();

#pragma unroll
        for (int j = 0; j < 16; j++) { Sa[j][0]=Sa[j][1]=Sa[j][2]=Sa[j][3]=0.f; }
#pragma unroll
        for (int ks = 0; ks < 8; ks++) {
            unsigned ah[4], al[4];
            ldsm4(ah, bQh + aoff + ks * 32);
            ldsm4(al, bQl + aoff + ks * 32);
#pragma unroll
            for (int fp = 0; fp < 8; fp++) {
                unsigned bh[4], bl[4];
                ldsm4(bh, bKh + bS + fp * (16 * CST * 2) + ks * 32);
                ldsm4(bl, bKl + bS + fp * (16 * CST * 2) + ks * 32);
#pragma unroll
                for (int hh = 0; hh < 2; hh++) {
                    float* c = Sa[fp * 2 + hh];
                    mma16816(c, ah, &bh[2 * hh]);
                    mma16816(c, ah, &bl[2 * hh]);
                    mma16816(c, al, &bh[2 * hh]);
                }
            }
        }

        float mx0 = -1e30f, mx1 = -1e30f;
#pragma unroll
        for (int j = 0; j < 16; j++) {
            mx0 = fmaxf(mx0, fmaxf(-Sa[j][0], -Sa[j][1]));
            mx1 = fmaxf(mx1, fmaxf(-Sa[j][2], -Sa[j][3]));
        }
        mx0 = fmaxf(mx0, __shfl_xor_sync(0xffffffffu, mx0, 1));
        mx0 = fmaxf(mx0, __shfl_xor_sync(0xffffffffu, mx0, 2));
        mx1 = fmaxf(mx1, __shfl_xor_sync(0xffffffffu, mx1, 1));
        mx1 = fmaxf(mx1, __shfl_xor_sync(0xffffffffu, mx1, 2));
        const float mn0 = fmaxf(m0r, mx0), mn1 = fmaxf(m1r, mx1);
        const float sc0 = __expf(m0r - mn0), sc1 = __expf(m1r - mn1);
        float rs0 = 0.f, rs1 = 0.f;
#pragma unroll
        for (int j = 0; j < 16; j++) {
            float p0 = __expf(-Sa[j][0] - mn0); Sa[j][0] = p0; rs0 += p0;
            float p1 = __expf(-Sa[j][1] - mn0); Sa[j][1] = p1; rs0 += p1;
            float p2 = __expf(-Sa[j][2] - mn1); Sa[j][2] = p2; rs1 += p2;
            float p3 = __expf(-Sa[j][3] - mn1); Sa[j][3] = p3; rs1 += p3;
        }
        rs0 += __shfl_xor_sync(0xffffffffu, rs0, 1);
        rs0 += __shfl_xor_sync(0xffffffffu, rs0, 2);
        rs1 += __shfl_xor_sync(0xffffffffu, rs1, 1);
        rs1 += __shfl_xor_sync(0xffffffffu, rs1, 2);
        l0r = l0r * sc0 + rs0;  l1r = l1r * sc1 + rs1;
        m0r = mn0;  m1r = mn1;
#pragma unroll
        for (int j = 0; j < 16; j++) {
            Oa[j][0] *= sc0; Oa[j][1] *= sc0;
            Oa[j][2] *= sc1; Oa[j][3] *= sc1;
        }

#pragma unroll
        for (int kp = 0; kp < 8; kp++) {
            const float* p0 = Sa[2 * kp];
            const float* p1 = Sa[2 * kp + 1];
            unsigned aPh[4], aPl[4];
            aPh[0] = packbf(p0[0], p0[1]);
            aPh[1] = packbf(p0[2], p0[3]);
            aPh[2] = packbf(p1[0], p1[1]);
            aPh[3] = packbf(p1[2], p1[3]);
            aPl[0] = packlo(p0[0], p0[1], aPh[0]);
            aPl[1] = packlo(p0[2], p0[3], aPh[1]);
            aPl[2] = packlo(p1[0], p1[1], aPh[2]);
            aPl[3] = packlo(p1[2], p1[3], aPh[3]);
#pragma unroll
            for (int fp = 0; fp < 8; fp++) {
                unsigned vh[4], vl[4];
                ldsm4t(vh, bKh + bT + kp * (16 * CST * 2) + fp * 32);
                ldsm4t(vl, bKl + bT + kp * (16 * CST * 2) + fp * 32);
#pragma unroll
                for (int hh = 0; hh < 2; hh++) {
                    float* c = Oa[fp * 2 + hh];
                    mma16816(c, aPh, &vh[2 * hh]);
                    mma16816(c, aPh, &vl[2 * hh]);
                    mma16816(c, aPl, &vh[2 * hh]);
                }
            }
        }
    }

    const float gam = *gptr;
    const float i0 = gam / l0r, i1 = gam / l1r;
    const int r0 = c0 + wid * 16 + g, r1 = r0 + 8;
    float* O = outg + (long)b * CCH * HW;
#pragma unroll
    for (int j = 0; j < 16; j++) {
        const int col = j * 8 + t * 2;
        const long o0 = (long)r0 * HW + col;
        const long o1 = (long)r1 * HW + col;
        float2 y0 = *(const float2*)&Y[o0];
        float2 y1v = *(const float2*)&Y[o1];
        float2 w0, w1;
        w0.x = Oa[j][0] * i0 + y0.x;  w0.y = Oa[j][1] * i0 + y0.y;
        w1.x = Oa[j][2] * i1 + y1v.x; w1.y = Oa[j][3] * i1 + y1v.y;
        *(float2*)&O[o0] = w0;
        *(float2*)&O[o1] = w1;
    }
}

// ------------------------ graph construction -------------------------------
__global__ void graph_build(const float* __restrict__ ip,
                            const float* __restrict__ adj,
                            float* __restrict__ graph)
{
    __shared__ float reda[4], redb[4];
    const int n = blockIdx.y, v = blockIdx.x, w = threadIdx.x;
    const long base = ((long)n * VV + v) * VV;

    const float sqv = ip[((long)n * VV + v) * VV + v];
    const float sqw = ip[((long)n * VV + w) * VV + w];
    const float e   = ip[base + w];

    float d2   = sqv + sqw - 2.f * e;
    float dist = sqrtf(fmaxf(d2, 1e-12f));
    float sim  = 2.f / (expf(dist) + 1.f);
    float av   = adj[base + w];
    if (w == v) { sim = 0.f; av = 0.f; }

    float s1 = warpSum(fabsf(sim));
    float s2 = warpSum(fabsf(av));
    if ((w & 31) == 0) { reda[w >> 5] = s1; redb[w >> 5] = s2; }
    __syncthreads();
    const float ssum = reda[0] + reda[1] + reda[2] + reda[3];
    const float asum = redb[0] + redb[1] + redb[2] + redb[3];

    graph[base + w] = 0.5f * (av / fmaxf(asum, 1e-12f) + sim / fmaxf(ssum, 1e-12f));
}

// ------------------------- batch-norm stats --------------------------------
__global__ void bn_stats(const float* __restrict__ hp,
                         float* __restrict__ mean, float* __restrict__ var,
                         int rows, int C)
{
    __shared__ float shs[8][32];
    __shared__ float shs2[8][32];
    const int lane = threadIdx.x & 31;
    const int ry   = threadIdx.x >> 5;
    const int c    = blockIdx.x * 32 + lane;

    float s = 0.f, s2 = 0.f;
    for (int r = ry; r < rows; r += 8) {
        float v = hp[(long)r * C + c];
        s += v; s2 += v * v;
    }
    shs[ry][lane] = s; shs2[ry][lane] = s2;
    __syncthreads();
    if (ry == 0) {
#pragma unroll
        for (int j = 1; j < 8; j++) { s += shs[j][lane]; s2 += shs2[j][lane]; }
        float mu = s / rows;
        mean[c] = mu;
        var[c]  = s2 / rows - mu * mu;
    }
}

// ------------------- BN apply + LeakyReLU + residual -----------------------
__global__ void bn_apply(const float* __restrict__ inp,
                         const float* __restrict__ hp,
                         const float* __restrict__ mean,
                         const float* __restrict__ var,
                         const float* __restrict__ bw,
                         const float* __restrict__ bb,
                         const float* __restrict__ gptr,
                         float* __restrict__ out, int total, int C)
{
    const int idx = blockIdx.x * blockDim.x + threadIdx.x;
    if (idx >= total) return;
    const int c = idx & (C - 1);
    const float g = *gptr;
    float vv = (hp[idx] - mean[c]) * rsqrtf(var[c] + 1e-5f) * bw[c] + bb[c];
    float lr = vv > 0.f ? vv : 0.1f * vv;
    out[idx] = inp[idx] + g * lr;
}

// ------------------------------ host side ----------------------------------
static void launch_gemm(int TA, int TB,
                        const float* A, const float* B, float* C,
                        int M, int N, int K,
                        long sA, long sB, long sC, int batch,
                        const float* bias,
                        const float* Res, long sRes,
                        float aH, const float* aD, cudaStream_t st)
{
    dim3 grid(N / 128, M / 128, batch);
    dim3 blk(512);
    if (TA == 0 && TB == 0)
        tgemm_kernel<0, 0><<<grid, blk, TSMEM, st>>>(A, B, C, M, N, K, sA, sB, sC, bias, Res, sRes, aH, aD);
    else if (TA == 1 && TB == 0)
        tgemm_kernel<1, 0><<<grid, blk, TSMEM, st>>>(A, B, C, M, N, K, sA, sB, sC, bias, Res, sRes, aH, aD);
    else
        tgemm_kernel<0, 1><<<grid, blk, TSMEM, st>>>(A, B, C, M, N, K, sA, sB, sC, bias, Res, sRes, aH, aD);
}

extern "C" void kernel_launch(void* const* d_in, const int* in_sizes, int n_in,
                              void* d_out, int out_size)
{
    const float* x     = (const float*)d_in[0];
    const float* vfeat = (const float*)d_in[1];
    const float* adj   = (const float*)d_in[2];
    const float* Wq    = (const float*)d_in[3];
    const float* bq    = (const float*)d_in[4];
    const float* Wk    = (const float*)d_in[5];
    const float* bk    = (const float*)d_in[6];
    const float* Wv    = (const float*)d_in[7];
    const float* bv    = (const float*)d_in[8];
    const float* gpam  = (const float*)d_in[9];
    const float* gcam  = (const float*)d_in[10];
    const float* Wg    = (const float*)d_in[11];
    const float* bnw   = (const float*)d_in[12];
    const float* bnb   = (const float*)d_in[13];
    const float* gg    = (const float*)d_in[14];
    float* out = (float*)d_out;

    float *q, *k, *v, *att1, *y1, *h, *ip, *graph, *hp, *gbuf, *mean, *var;
    cudaGetSymbolAddress((void**)&q,    d_q);
    cudaGetSymbolAddress((void**)&k,    d_k);
    cudaGetSymbolAddress((void**)&v,    d_v);
    cudaGetSymbolAddress((void**)&att1, d_att1);
    cudaGetSymbolAddress((void**)&y1,   d_y1);
    cudaGetSymbolAddress((void**)&h,    d_h);
    cudaGetSymbolAddress((void**)&ip,   d_ip);
    cudaGetSymbolAddress((void**)&graph,d_graph);
    cudaGetSymbolAddress((void**)&hp,   d_hp);
    cudaGetSymbolAddress((void**)&gbuf, d_gbuf);
    cudaGetSymbolAddress((void**)&mean, d_mean);
    cudaGetSymbolAddress((void**)&var,  d_var);

    static int inited = 0;
    if (!inited) {
        cudaFuncSetAttribute(tgemm_kernel<0, 0>,
                             cudaFuncAttributeMaxDynamicSharedMemorySize, TSMEM);
        cudaFuncSetAttribute(tgemm_kernel<1, 0>,
                             cudaFuncAttributeMaxDynamicSharedMemorySize, TSMEM);
        cudaFuncSetAttribute(tgemm_kernel<0, 1>,
                             cudaFuncAttributeMaxDynamicSharedMemorySize, TSMEM);
        cudaFuncSetAttribute(cam_tc_kernel,
                             cudaFuncAttributeMaxDynamicSharedMemorySize, CAM_SMEM);
        inited = 1;
    }
    static cudaStream_t s1 = [](){ cudaStream_t s;
        cudaStreamCreateWithFlags(&s, cudaStreamNonBlocking); return s; }();
    static cudaStream_t s2 = [](){ cudaStream_t s;
        cudaStreamCreateWithFlags(&s, cudaStreamNonBlocking); return s; }();
    static cudaEvent_t evF = [](){ cudaEvent_t e;
        cudaEventCreateWithFlags(&e, cudaEventDisableTiming); return e; }();
    static cudaEvent_t evK = [](){ cudaEvent_t e;
        cudaEventCreateWithFlags(&e, cudaEventDisableTiming); return e; }();
    static cudaEvent_t evV = [](){ cudaEvent_t e;
        cudaEventCreateWithFlags(&e, cudaEventDisableTiming); return e; }();
    static cudaEvent_t evJ = [](){ cudaEvent_t e;
        cudaEventCreateWithFlags(&e, cudaEventDisableTiming); return e; }();

    const long CHW = (long)CCH * HW;          // 262144
    const long QHW = (long)C8 * HW;           // 32768
    const long GST = (long)VV * CCH;          // 262144
    cudaStream_t s0 = 0;

    // ---- fork: s1 gets Wk+Wv, s2 gets graph chain ----
    cudaEventRecord(evF, s0);
    cudaStreamWaitEvent(s1, evF, 0);
    cudaStreamWaitEvent(s2, evF, 0);

    // ---------------- PAM ----------------
    launch_gemm(0, 0, Wq, x, q, C8,  HW, CCH, 0, CHW, QHW, BSZ, bq, nullptr, 0, 1.f, nullptr, s0);
    launch_gemm(0, 0, Wk, x, k, C8,  HW, CCH, 0, CHW, QHW, BSZ, bk, nullptr, 0, 1.f, nullptr, s1);
    cudaEventRecord(evK, s1);
    launch_gemm(0, 0, Wv, x, v, CCH, HW, CCH, 0, CHW, CHW, BSZ, bv, nullptr, 0, 1.f, nullptr, s1);
    cudaEventRecord(evV, s1);

    cudaStreamWaitEvent(s0, evK, 0);
    launch_gemm(1, 0, q, k, att1, HW, HW, C8, QHW, QHW, (long)HW * HW, BSZ,
                nullptr, nullptr, 0, 1.f, nullptr, s0);
    softmax_kernel<<<BSZ * HW, 128, 0, s0>>>(att1, HW);
    cudaStreamWaitEvent(s0, evV, 0);
    launch_gemm(0, 1, v, att1, y1, CCH, HW, HW, CHW, (long)HW * HW, CHW, BSZ,
                nullptr, x, CHW, 0.f, gpam, s0);

    // ---------------- CAM (s0, tensor-core flash) ----------------
    {
        dim3 grid(CCH / 128, BSZ);
        cam_tc_kernel<<<grid, 256, CAM_SMEM, s0>>>(y1, gcam, out);
    }

    // ------------- Graph layers (s2) -------------
    const float* inp = vfeat;
    for (int i = 0; i < GNUM; i++) {
        float* outg = (i == GNUM - 1) ? (out + (long)BSZ * CCH * HW) : gbuf;
        launch_gemm(0, 1, inp, Wg + (long)i * CCH * CCH, h,
                    NV * VV, CCH, CCH, 0, 0, 0, 1, nullptr, nullptr, 0, 1.f, nullptr, s2);
        launch_gemm(0, 1, inp, inp, ip, VV, VV, CCH, GST, GST, (long)VV * VV, NV,
                    nullptr, nullptr, 0, 1.f, nullptr, s2);
        graph_build<<<dim3(VV, NV), VV, 0, s2>>>(ip, adj, graph);
        launch_gemm(0, 0, graph, h, hp, VV, CCH, VV, (long)VV * VV, GST, GST, NV,
                    nullptr, nullptr, 0, 1.f, nullptr, s2);
        bn_stats<<<CCH / 32, 256, 0, s2>>>(hp, mean, var, NV * VV, CCH);
        bn_apply<<<(NV * VV * CCH + 255) / 256, 256, 0, s2>>>(
            inp, hp, mean, var, bnw + (long)i * CCH, bnb + (long)i * CCH,
            gg + i, outg, NV * VV * CCH, CCH);
        inp = outg;
    }

    // ---- join ----
    cudaEventRecord(evJ, s2);
    cudaStreamWaitEvent(s0, evJ, 0);
}

// round 8
// speedup vs baseline: 1.1454x; 1.1454x over previous
#include <cuda_runtime.h>
#include <cuda_bf16.h>
#include <math.h>

// ---------------------------------------------------------------------------
// Problem constants
// ---------------------------------------------------------------------------
#define BSZ   16
#define CCH   2048
#define HW    128
#define C8    256
#define NV    16
#define VV    128
#define GNUM  2

// ------------------------- scratch (device globals) ------------------------
__device__ __align__(256) float d_q   [BSZ * C8 * HW];
__device__ __align__(256) float d_k   [BSZ * C8 * HW];
__device__ __align__(256) float d_v   [BSZ * CCH * HW];
__device__ __align__(256) float d_att1[BSZ * HW * HW];
__device__ __align__(256) float d_y1  [BSZ * CCH * HW];
__device__ __align__(256) float d_h   [NV * VV * CCH];
__device__ __align__(256) float d_ip  [NV * VV * VV];
__device__ __align__(256) float d_graph[NV * VV * VV];
__device__ __align__(256) float d_hp  [NV * VV * CCH];
__device__ __align__(256) float d_gbuf[NV * VV * CCH];
__device__ __align__(256) float d_mean[CCH];
__device__ __align__(256) float d_var [CCH];

// ---------------------- shared mma/ldsm/split helpers -----------------------
__device__ __forceinline__ void ldsm4(unsigned* r, unsigned addr) {
    asm volatile("ldmatrix.sync.aligned.m8n8.x4.shared.b16 {%0,%1,%2,%3}, [%4];"
        : "=r"(r[0]), "=r"(r[1]), "=r"(r[2]), "=r"(r[3]) : "r"(addr));
}
__device__ __forceinline__ void ldsm4t(unsigned* r, unsigned addr) {
    asm volatile("ldmatrix.sync.aligned.m8n8.x4.trans.shared.b16 {%0,%1,%2,%3}, [%4];"
        : "=r"(r[0]), "=r"(r[1]), "=r"(r[2]), "=r"(r[3]) : "r"(addr));
}
__device__ __forceinline__ void mma16816(float* c, const unsigned* a, const unsigned* b) {
    asm volatile("mma.sync.aligned.m16n8k16.row.col.f32.bf16.bf16.f32 "
        "{%0,%1,%2,%3}, {%4,%5,%6,%7}, {%8,%9}, {%0,%1,%2,%3};"
        : "+f"(c[0]), "+f"(c[1]), "+f"(c[2]), "+f"(c[3])
        : "r"(a[0]), "r"(a[1]), "r"(a[2]), "r"(a[3]), "r"(b[0]), "r"(b[1]));
}
__device__ __forceinline__ void bsplit(float x, __nv_bfloat16& h, __nv_bfloat16& l) {
    h = __float2bfloat16(x);
    l = __float2bfloat16(x - __bfloat162float(h));
}
__device__ __forceinline__ unsigned packbf(float a, float b) {
    __nv_bfloat162 p; p.x = __float2bfloat16(a); p.y = __float2bfloat16(b);
    return *(unsigned*)&p;
}
__device__ __forceinline__ unsigned packlo(float a, float b, unsigned hipack) {
    __nv_bfloat162 h = *(__nv_bfloat162*)&hipack;
    return packbf(a - __bfloat162float(h.x), b - __bfloat162float(h.y));
}

// ======================= bf16-split tensor-core GEMM ========================
// R6-measured-best shape: 256 threads, 8 warps, warp tile 32x64.
// Block tile 128x128, K-step 32, double-buffered. acc = AhBh + AhBl + AlBh.
#define TST   40
#define TTILE (128 * TST)
#define TSMEM (2 * 4 * TTILE * 2)

template<int TA, int TB>
__global__ __launch_bounds__(256)
void tgemm_kernel(const float* __restrict__ Ag, const float* __restrict__ Bg,
                  float* __restrict__ Cg,
                  int M, int N, int K,
                  long sA, long sB, long sC,
                  const float* __restrict__ bias,
                  const float* __restrict__ Res, long sRes,
                  float alphaH, const float* __restrict__ alphaD)
{
    extern __shared__ __align__(16) __nv_bfloat16 ts[];

    const int bz = blockIdx.z;
    const float* A = Ag + (long)bz * sA;
    const float* B = Bg + (long)bz * sB;
    float*       C = Cg + (long)bz * sC;

    const int m0 = blockIdx.y * 128;
    const int n0 = blockIdx.x * 128;
    const int tid  = threadIdx.x;
    const int wid  = tid >> 5;
    const int lane = tid & 31;
    const int warp_m = (wid >> 1) * 32;
    const int warp_n = (wid & 1) * 64;
    const int mi = lane >> 3, ri = lane & 7;
    const int g  = lane >> 2, t  = lane & 3;

    const unsigned sbase = (unsigned)__cvta_generic_to_shared(ts);

    unsigned aoff[2], boff[4];
#pragma unroll
    for (int fi = 0; fi < 2; fi++)
        aoff[fi] = ((warp_m + fi * 16 + ((mi & 1) << 3) + ri) * TST + ((mi >> 1) << 3)) * 2;
#pragma unroll
    for (int fp = 0; fp < 4; fp++)
        boff[fp] = ((warp_n + fp * 16 + ((mi >> 1) << 3) + ri) * TST + ((mi & 1) << 3)) * 2;

    float acc[2][8][4];
#pragma unroll
    for (int i = 0; i < 2; i++)
#pragma unroll
        for (int j = 0; j < 8; j++)
#pragma unroll
            for (int q = 0; q < 4; q++) acc[i][j][q] = 0.f;

    float4 pa[4], pb[4];
    const int rA = tid >> 1, cA = (tid & 1) * 16;
    const int kA = tid >> 3, mA = (tid & 7) * 16;

#define LOADG(k0)                                                              \
    do {                                                                       \
        if (TA == 0) {                                                         \
            _Pragma("unroll")                                                  \
            for (int j = 0; j < 4; j++)                                        \
                pa[j] = *(const float4*)&A[(long)(m0 + rA) * K + (k0) + cA + 4 * j]; \
        } else {                                                               \
            _Pragma("unroll")                                                  \
            for (int j = 0; j < 4; j++)                                        \
                pa[j] = *(const float4*)&A[(long)((k0) + kA) * M + m0 + mA + 4 * j]; \
        }                                                                      \
        if (TB == 1) {                                                         \
            _Pragma("unroll")                                                  \
            for (int j = 0; j < 4; j++)                                        \
                pb[j] = *(const float4*)&B[(long)(n0 + rA) * K + (k0) + cA + 4 * j]; \
        } else {                                                               \
            _Pragma("unroll")                                                  \
            for (int j = 0; j < 4; j++)                                        \
                pb[j] = *(const float4*)&B[(long)((k0) + kA) * N + n0 + mA + 4 * j]; \
        }                                                                      \
    } while (0)

#define CVSTORE(bf)                                                            \
    do {                                                                       \
        __nv_bfloat16* Ah = ts + ((bf) * 4 + 0) * TTILE;                       \
        __nv_bfloat16* Al = ts + ((bf) * 4 + 1) * TTILE;                       \
        __nv_bfloat16* Bh = ts + ((bf) * 4 + 2) * TTILE;                       \
        __nv_bfloat16* Bl = ts + ((bf) * 4 + 3) * TTILE;                       \
        _Pragma("unroll")                                                      \
        for (int j = 0; j < 4; j++) {                                          \
            float v[4] = { pa[j].x, pa[j].y, pa[j].z, pa[j].w };               \
            __nv_bfloat16 h[4], l[4];                                          \
            _Pragma("unroll")                                                  \
            for (int i = 0; i < 4; i++) bsplit(v[i], h[i], l[i]);              \
            if (TA == 0) {                                                     \
                int base = rA * TST + cA + 4 * j;                              \
                __nv_bfloat162 h01; h01.x = h[0]; h01.y = h[1];                \
                __nv_bfloat162 h23; h23.x = h[2]; h23.y = h[3];                \
                __nv_bfloat162 l01; l01.x = l[0]; l01.y = l[1];                \
                __nv_bfloat162 l23; l23.x = l[2]; l23.y = l[3];                \
                *(__nv_bfloat162*)(Ah + base)     = h01;                       \
                *(__nv_bfloat162*)(Ah + base + 2) = h23;                       \
                *(__nv_bfloat162*)(Al + base)     = l01;                       \
                *(__nv_bfloat162*)(Al + base + 2) = l23;                       \
            } else {                                                           \
                _Pragma("unroll")                                              \
                for (int i = 0; i < 4; i++) {                                  \
                    int row = mA + 4 * j + i;                                  \
                    Ah[row * TST + kA] = h[i];                                 \
                    Al[row * TST + kA] = l[i];                                 \
                }                                                              \
            }                                                                  \
        }                                                                      \
        _Pragma("unroll")                                                      \
        for (int j = 0; j < 4; j++) {                                          \
            float v[4] = { pb[j].x, pb[j].y, pb[j].z, pb[j].w };               \
            __nv_bfloat16 h[4], l[4];                                          \
            _Pragma("unroll")                                                  \
            for (int i = 0; i < 4; i++) bsplit(v[i], h[i], l[i]);              \
            if (TB == 1) {                                                     \
                int base = rA * TST + cA + 4 * j;                              \
                __nv_bfloat162 h01; h01.x = h[0]; h01.y = h[1];                \
                __nv_bfloat162 h23; h23.x = h[2]; h23.y = h[3];                \
                __nv_bfloat162 l01; l01.x = l[0]; l01.y = l[1];                \
                __nv_bfloat162 l23; l23.x = l[2]; l23.y = l[3];                \
                *(__nv_bfloat162*)(Bh + base)     = h01;                       \
                *(__nv_bfloat162*)(Bh + base + 2) = h23;                       \
                *(__nv_bfloat162*)(Bl + base)     = l01;                       \
                *(__nv_bfloat162*)(Bl + base + 2) = l23;                       \
            } else {                                                           \
                _Pragma("unroll")                                              \
                for (int i = 0; i < 4; i++) {                                  \
                    int row = mA + 4 * j + i;                                  \
                    Bh[row * TST + kA] = h[i];                                 \
                    Bl[row * TST + kA] = l[i];                                 \
                }                                                              \
            }                                                                  \
        }                                                                      \
    } while (0)

#define MMASTEP(bf)                                                            \
    do {                                                                       \
        const unsigned bAh = sbase + ((bf) * 4 + 0) * TTILE * 2;               \
        const unsigned bAl = sbase + ((bf) * 4 + 1) * TTILE * 2;               \
        const unsigned bBh = sbase + ((bf) * 4 + 2) * TTILE * 2;               \
        const unsigned bBl = sbase + ((bf) * 4 + 3) * TTILE * 2;               \
        _Pragma("unroll")                                                      \
        for (int kk = 0; kk < 2; kk++) {                                       \
            unsigned ah[2][4], al[2][4], bh[4][4], bl[4][4];                   \
            _Pragma("unroll")                                                  \
            for (int fi = 0; fi < 2; fi++) {                                   \
                ldsm4(ah[fi], bAh + aoff[fi] + kk * 32);                       \
                ldsm4(al[fi], bAl + aoff[fi] + kk * 32);                       \
            }                                                                  \
            _Pragma("unroll")                                                  \
            for (int fp = 0; fp < 4; fp++) {                                   \
                ldsm4(bh[fp], bBh + boff[fp] + kk * 32);                       \
                ldsm4(bl[fp], bBl + boff[fp] + kk * 32);                       \
            }                                                                  \
            _Pragma("unroll")                                                  \
            for (int fi = 0; fi < 2; fi++)                                     \
                _Pragma("unroll")                                              \
                for (int fp = 0; fp < 4; fp++)                                 \
                    _Pragma("unroll")                                          \
                    for (int hh = 0; hh < 2; hh++) {                           \
                        float* c = acc[fi][fp * 2 + hh];                       \
                        mma16816(c, ah[fi], &bh[fp][2 * hh]);                  \
                        mma16816(c, ah[fi], &bl[fp][2 * hh]);                  \
                        mma16816(c, al[fi], &bh[fp][2 * hh]);                  \
                    }                                                          \
        }                                                                      \
    } while (0)

    LOADG(0);
    CVSTORE(0);
    __syncthreads();

    const int nt = K / 32;
    for (int tI = 0; tI < nt; tI++) {
        if (tI + 1 < nt) LOADG((tI + 1) * 32);
        MMASTEP(tI & 1);
        if (tI + 1 < nt) {
            CVSTORE((tI + 1) & 1);
            __syncthreads();
        }
    }

    const float alpha = alphaD ? *alphaD : alphaH;
#pragma unroll
    for (int fi = 0; fi < 2; fi++) {
        const int m = m0 + warp_m + fi * 16 + g;
        const float bi0 = bias ? __ldg(&bias[m])     : 0.f;
        const float bi1 = bias ? __ldg(&bias[m + 8]) : 0.f;
#pragma unroll
        for (int fj = 0; fj < 8; fj++) {
            const int n = n0 + warp_n + fj * 8 + t * 2;
            const float* c = acc[fi][fj];
            const long off0 = (long)m * N + n;
            const long off1 = (long)(m + 8) * N + n;
            float2 o0, o1;
            o0.x = alpha * c[0] + bi0; o0.y = alpha * c[1] + bi0;
            o1.x = alpha * c[2] + bi1; o1.y = alpha * c[3] + bi1;
            if (Res) {
                float2 r0 = *(const float2*)&Res[(long)bz * sRes + off0];
                float2 r1 = *(const float2*)&Res[(long)bz * sRes + off1];
                o0.x += r0.x; o0.y += r0.y;
                o1.x += r1.x; o1.y += r1.y;
            }
            *(float2*)&C[off0] = o0;
            *(float2*)&C[off1] = o1;
        }
    }
#undef LOADG
#undef CVSTORE
#undef MMASTEP
}

// --------------------------- reductions ------------------------------------
__device__ __forceinline__ float warpMax(float v) {
#pragma unroll
    for (int o = 16; o; o >>= 1) v = fmaxf(v, __shfl_xor_sync(0xffffffffu, v, o));
    return v;
}
__device__ __forceinline__ float warpSum(float v) {
#pragma unroll
    for (int o = 16; o; o >>= 1) v += __shfl_xor_sync(0xffffffffu, v, o);
    return v;
}

// in-place row softmax; one block per row
__global__ void softmax_kernel(float* __restrict__ d, int ncols)
{
    __shared__ float red[32];
    __shared__ float bcast;
    const long row = blockIdx.x;
    float* p = d + row * (long)ncols;
    const int tid = threadIdx.x, nt = blockDim.x;

    float m = -1e30f;
    for (int i = tid; i < ncols; i += nt) m = fmaxf(m, p[i]);
    m = warpMax(m);
    if ((tid & 31) == 0) red[tid >> 5] = m;
    __syncthreads();
    if (tid < 32) {
        float v = (tid < (nt >> 5)) ? red[tid] : -1e30f;
        v = warpMax(v);
        if (tid == 0) bcast = v;
    }
    __syncthreads();
    m = bcast;

    float s = 0.f;
    for (int i = tid; i < ncols; i += nt) {
        float e = __expf(p[i] - m);
        p[i] = e;
        s += e;
    }
    __syncthreads();
    s = warpSum(s);
    if ((tid & 31) == 0) red[tid >> 5] = s;
    __syncthreads();
    if (tid < 32) {
        float v = (tid < (nt >> 5)) ? red[tid] : 0.f;
        v = warpSum(v);
        if (tid == 0) bcast = v;
    }
    __syncthreads();
    const float inv = 1.f / bcast;
    for (int i = tid; i < ncols; i += nt) p[i] *= inv;
}

// ================= tensor-core fused CAM (flash style) ======================
#define CST   136
#define CTILE (128 * CST)
#define CAM_SMEM (4 * CTILE * 2)

__global__ __launch_bounds__(256)
void cam_tc_kernel(const float* __restrict__ y1g,
                   const float* __restrict__ gptr,
                   float* __restrict__ outg)
{
    extern __shared__ __align__(16) __nv_bfloat16 cs[];
    __nv_bfloat16* Qh = cs;
    __nv_bfloat16* Ql = cs + CTILE;
    __nv_bfloat16* Kh = cs + 2 * CTILE;
    __nv_bfloat16* Kl = cs + 3 * CTILE;

    const int b  = blockIdx.y;
    const int c0 = blockIdx.x * 128;
    const float* Y = y1g + (long)b * CCH * HW;

    const int tid = threadIdx.x, wid = tid >> 5, lane = tid & 31;
    const int mi = lane >> 3, ri = lane & 7, g = lane >> 2, t = lane & 3;

    const unsigned sb  = (unsigned)__cvta_generic_to_shared(cs);
    const unsigned bQh = sb;
    const unsigned bQl = sb + CTILE * 2;
    const unsigned bKh = sb + 2 * CTILE * 2;
    const unsigned bKl = sb + 3 * CTILE * 2;

    const unsigned aoff = ((wid * 16 + ((mi & 1) << 3) + ri) * CST + ((mi >> 1) << 3)) * 2;
    const unsigned bS = ((((mi >> 1) << 3) + ri) * CST + ((mi & 1) << 3)) * 2;
    const unsigned bT = ((((mi & 1) << 3) + ri) * CST + ((mi >> 1) << 3)) * 2;

    for (int idx = tid; idx < 128 * 32; idx += 256) {
        int r = idx >> 5, hw = (idx & 31) * 4;
        float4 v = *(const float4*)&Y[(long)(c0 + r) * HW + hw];
        __nv_bfloat16 h0,l0,h1,l1,h2,l2,h3,l3;
        bsplit(v.x,h0,l0); bsplit(v.y,h1,l1); bsplit(v.z,h2,l2); bsplit(v.w,h3,l3);
        __nv_bfloat162 a; __nv_bfloat162 c;
        __nv_bfloat162* ph = (__nv_bfloat162*)(Qh + r * CST + hw);
        __nv_bfloat162* pl = (__nv_bfloat162*)(Ql + r * CST + hw);
        a.x = h0; a.y = h1; ph[0] = a;  a.x = h2; a.y = h3; ph[1] = a;
        c.x = l0; c.y = l1; pl[0] = c;  c.x = l2; c.y = l3; pl[1] = c;
    }

    float Sa[16][4], Oa[16][4];
    float m0r = -1e30f, m1r = -1e30f, l0r = 0.f, l1r = 0.f;
#pragma unroll
    for (int j = 0; j < 16; j++) { Oa[j][0]=Oa[j][1]=Oa[j][2]=Oa[j][3]=0.f; }

    for (int tI = 0; tI < 16; tI++) {
        __syncthreads();
        for (int idx = tid; idx < 128 * 32; idx += 256) {
            int d = idx >> 5, hw = (idx & 31) * 4;
            float4 v = *(const float4*)&Y[(long)(tI * 128 + d) * HW + hw];
            __nv_bfloat16 h0,l0,h1,l1,h2,l2,h3,l3;
            bsplit(v.x,h0,l0); bsplit(v.y,h1,l1); bsplit(v.z,h2,l2); bsplit(v.w,h3,l3);
            __nv_bfloat162 a; __nv_bfloat162 c;
            __nv_bfloat162* ph = (__nv_bfloat162*)(Kh + d * CST + hw);
            __nv_bfloat162* pl = (__nv_bfloat162*)(Kl + d * CST + hw);
            a.x = h0; a.y = h1; ph[0] = a;  a.x = h2; a.y = h3; ph[1] = a;
            c.x = l0; c.y = l1; pl[0] = c;  c.x = l2; c.y = l3; pl[1] = c;
        }
        __syncthreads();

#pragma unroll
        for (int j = 0; j < 16; j++) { Sa[j][0]=Sa[j][1]=Sa[j][2]=Sa[j][3]=0.f; }
#pragma unroll
        for (int ks = 0; ks < 8; ks++) {
            unsigned ah[4], al[4];
            ldsm4(ah, bQh + aoff + ks * 32);
            ldsm4(al, bQl + aoff + ks * 32);
#pragma unroll
            for (int fp = 0; fp < 8; fp++) {
                unsigned bh[4], bl[4];
                ldsm4(bh, bKh + bS + fp * (16 * CST * 2) + ks * 32);
                ldsm4(bl, bKl + bS + fp * (16 * CST * 2) + ks * 32);
#pragma unroll
                for (int hh = 0; hh < 2; hh++) {
                    float* c = Sa[fp * 2 + hh];
                    mma16816(c, ah, &bh[2 * hh]);
                    mma16816(c, ah, &bl[2 * hh]);
                    mma16816(c, al, &bh[2 * hh]);
                }
            }
        }

        float mx0 = -1e30f, mx1 = -1e30f;
#pragma unroll
        for (int j = 0; j < 16; j++) {
            mx0 = fmaxf(mx0, fmaxf(-Sa[j][0], -Sa[j][1]));
            mx1 = fmaxf(mx1, fmaxf(-Sa[j][2], -Sa[j][3]));
        }
        mx0 = fmaxf(mx0, __shfl_xor_sync(0xffffffffu, mx0, 1));
        mx0 = fmaxf(mx0, __shfl_xor_sync(0xffffffffu, mx0, 2));
        mx1 = fmaxf(mx1, __shfl_xor_sync(0xffffffffu, mx1, 1));
        mx1 = fmaxf(mx1, __shfl_xor_sync(0xffffffffu, mx1, 2));
        const float mn0 = fmaxf(m0r, mx0), mn1 = fmaxf(m1r, mx1);
        const float sc0 = __expf(m0r - mn0), sc1 = __expf(m1r - mn1);
        float rs0 = 0.f, rs1 = 0.f;
#pragma unroll
        for (int j = 0; j < 16; j++) {
            float p0 = __expf(-Sa[j][0] - mn0); Sa[j][0] = p0; rs0 += p0;
            float p1 = __expf(-Sa[j][1] - mn0); Sa[j][1] = p1; rs0 += p1;
            float p2 = __expf(-Sa[j][2] - mn1); Sa[j][2] = p2; rs1 += p2;
            float p3 = __expf(-Sa[j][3] - mn1); Sa[j][3] = p3; rs1 += p3;
        }
        rs0 += __shfl_xor_sync(0xffffffffu, rs0, 1);
        rs0 += __shfl_xor_sync(0xffffffffu, rs0, 2);
        rs1 += __shfl_xor_sync(0xffffffffu, rs1, 1);
        rs1 += __shfl_xor_sync(0xffffffffu, rs1, 2);
        l0r = l0r * sc0 + rs0;  l1r = l1r * sc1 + rs1;
        m0r = mn0;  m1r = mn1;
#pragma unroll
        for (int j = 0; j < 16; j++) {
            Oa[j][0] *= sc0; Oa[j][1] *= sc0;
            Oa[j][2] *= sc1; Oa[j][3] *= sc1;
        }

#pragma unroll
        for (int kp = 0; kp < 8; kp++) {
            const float* p0 = Sa[2 * kp];
            const float* p1 = Sa[2 * kp + 1];
            unsigned aPh[4], aPl[4];
            aPh[0] = packbf(p0[0], p0[1]);
            aPh[1] = packbf(p0[2], p0[3]);
            aPh[2] = packbf(p1[0], p1[1]);
            aPh[3] = packbf(p1[2], p1[3]);
            aPl[0] = packlo(p0[0], p0[1], aPh[0]);
            aPl[1] = packlo(p0[2], p0[3], aPh[1]);
            aPl[2] = packlo(p1[0], p1[1], aPh[2]);
            aPl[3] = packlo(p1[2], p1[3], aPh[3]);
#pragma unroll
            for (int fp = 0; fp < 8; fp++) {
                unsigned vh[4], vl[4];
                ldsm4t(vh, bKh + bT + kp * (16 * CST * 2) + fp * 32);
                ldsm4t(vl, bKl + bT + kp * (16 * CST * 2) + fp * 32);
#pragma unroll
                for (int hh = 0; hh < 2; hh++) {
                    float* c = Oa[fp * 2 + hh];
                    mma16816(c, aPh, &vh[2 * hh]);
                    mma16816(c, aPh, &vl[2 * hh]);
                    mma16816(c, aPl, &vh[2 * hh]);
                }
            }
        }
    }

    const float gam = *gptr;
    const float i0 = gam / l0r, i1 = gam / l1r;
    const int r0 = c0 + wid * 16 + g, r1 = r0 + 8;
    float* O = outg + (long)b * CCH * HW;
#pragma unroll
    for (int j = 0; j < 16; j++) {
        const int col = j * 8 + t * 2;
        const long o0 = (long)r0 * HW + col;
        const long o1 = (long)r1 * HW + col;
        float2 y0 = *(const float2*)&Y[o0];
        float2 y1v = *(const float2*)&Y[o1];
        float2 w0, w1;
        w0.x = Oa[j][0] * i0 + y0.x;  w0.y = Oa[j][1] * i0 + y0.y;
        w1.x = Oa[j][2] * i1 + y1v.x; w1.y = Oa[j][3] * i1 + y1v.y;
        *(float2*)&O[o0] = w0;
        *(float2*)&O[o1] = w1;
    }
}

// ------------------------ graph construction -------------------------------
__global__ void graph_build(const float* __restrict__ ip,
                            const float* __restrict__ adj,
                            float* __restrict__ graph)
{
    __shared__ float reda[4], redb[4];
    const int n = blockIdx.y, v = blockIdx.x, w = threadIdx.x;
    const long base = ((long)n * VV + v) * VV;

    const float sqv = ip[((long)n * VV + v) * VV + v];
    const float sqw = ip[((long)n * VV + w) * VV + w];
    const float e   = ip[base + w];

    float d2   = sqv + sqw - 2.f * e;
    float dist = sqrtf(fmaxf(d2, 1e-12f));
    float sim  = 2.f / (expf(dist) + 1.f);
    float av   = adj[base + w];
    if (w == v) { sim = 0.f; av = 0.f; }

    float s1 = warpSum(fabsf(sim));
    float s2 = warpSum(fabsf(av));
    if ((w & 31) == 0) { reda[w >> 5] = s1; redb[w >> 5] = s2; }
    __syncthreads();
    const float ssum = reda[0] + reda[1] + reda[2] + reda[3];
    const float asum = redb[0] + redb[1] + redb[2] + redb[3];

    graph[base + w] = 0.5f * (av / fmaxf(asum, 1e-12f) + sim / fmaxf(ssum, 1e-12f));
}

// ------------------------- batch-norm stats --------------------------------
__global__ void bn_stats(const float* __restrict__ hp,
                         float* __restrict__ mean, float* __restrict__ var,
                         int rows, int C)
{
    __shared__ float shs[8][32];
    __shared__ float shs2[8][32];
    const int lane = threadIdx.x & 31;
    const int ry   = threadIdx.x >> 5;
    const int c    = blockIdx.x * 32 + lane;

    float s = 0.f, s2 = 0.f;
    for (int r = ry; r < rows; r += 8) {
        float v = hp[(long)r * C + c];
        s += v; s2 += v * v;
    }
    shs[ry][lane] = s; shs2[ry][lane] = s2;
    __syncthreads();
    if (ry == 0) {
#pragma unroll
        for (int j = 1; j < 8; j++) { s += shs[j][lane]; s2 += shs2[j][lane]; }
        float mu = s / rows;
        mean[c] = mu;
        var[c]  = s2 / rows - mu * mu;
    }
}

// ------------------- BN apply + LeakyReLU + residual -----------------------
__global__ void bn_apply(const float* __restrict__ inp,
                         const float* __restrict__ hp,
                         const float* __restrict__ mean,
                         const float* __restrict__ var,
                         const float* __restrict__ bw,
                         const float* __restrict__ bb,
                         const float* __restrict__ gptr,
                         float* __restrict__ out, int total, int C)
{
    const int idx = blockIdx.x * blockDim.x + threadIdx.x;
    if (idx >= total) return;
    const int c = idx & (C - 1);
    const float g = *gptr;
    float vv = (hp[idx] - mean[c]) * rsqrtf(var[c] + 1e-5f) * bw[c] + bb[c];
    float lr = vv > 0.f ? vv : 0.1f * vv;
    out[idx] = inp[idx] + g * lr;
}

// ------------------------------ host side ----------------------------------
static void launch_gemm(int TA, int TB,
                        const float* A, const float* B, float* C,
                        int M, int N, int K,
                        long sA, long sB, long sC, int batch,
                        const float* bias,
                        const float* Res, long sRes,
                        float aH, const float* aD, cudaStream_t st)
{
    dim3 grid(N / 128, M / 128, batch);
    dim3 blk(256);
    if (TA == 0 && TB == 0)
        tgemm_kernel<0, 0><<<grid, blk, TSMEM, st>>>(A, B, C, M, N, K, sA, sB, sC, bias, Res, sRes, aH, aD);
    else if (TA == 1 && TB == 0)
        tgemm_kernel<1, 0><<<grid, blk, TSMEM, st>>>(A, B, C, M, N, K, sA, sB, sC, bias, Res, sRes, aH, aD);
    else
        tgemm_kernel<0, 1><<<grid, blk, TSMEM, st>>>(A, B, C, M, N, K, sA, sB, sC, bias, Res, sRes, aH, aD);
}

extern "C" void kernel_launch(void* const* d_in, const int* in_sizes, int n_in,
                              void* d_out, int out_size)
{
    const float* x     = (const float*)d_in[0];
    const float* vfeat = (const float*)d_in[1];
    const float* adj   = (const float*)d_in[2];
    const float* Wq    = (const float*)d_in[3];
    const float* bq    = (const float*)d_in[4];
    const float* Wk    = (const float*)d_in[5];
    const float* bk    = (const float*)d_in[6];
    const float* Wv    = (const float*)d_in[7];
    const float* bv    = (const float*)d_in[8];
    const float* gpam  = (const float*)d_in[9];
    const float* gcam  = (const float*)d_in[10];
    const float* Wg    = (const float*)d_in[11];
    const float* bnw   = (const float*)d_in[12];
    const float* bnb   = (const float*)d_in[13];
    const float* gg    = (const float*)d_in[14];
    float* out = (float*)d_out;

    float *q, *k, *v, *att1, *y1, *h, *ip, *graph, *hp, *gbuf, *mean, *var;
    cudaGetSymbolAddress((void**)&q,    d_q);
    cudaGetSymbolAddress((void**)&k,    d_k);
    cudaGetSymbolAddress((void**)&v,    d_v);
    cudaGetSymbolAddress((void**)&att1, d_att1);
    cudaGetSymbolAddress((void**)&y1,   d_y1);
    cudaGetSymbolAddress((void**)&h,    d_h);
    cudaGetSymbolAddress((void**)&ip,   d_ip);
    cudaGetSymbolAddress((void**)&graph,d_graph);
    cudaGetSymbolAddress((void**)&hp,   d_hp);
    cudaGetSymbolAddress((void**)&gbuf, d_gbuf);
    cudaGetSymbolAddress((void**)&mean, d_mean);
    cudaGetSymbolAddress((void**)&var,  d_var);

    static int inited = 0;
    if (!inited) {
        cudaFuncSetAttribute(tgemm_kernel<0, 0>,
                             cudaFuncAttributeMaxDynamicSharedMemorySize, TSMEM);
        cudaFuncSetAttribute(tgemm_kernel<1, 0>,
                             cudaFuncAttributeMaxDynamicSharedMemorySize, TSMEM);
        cudaFuncSetAttribute(tgemm_kernel<0, 1>,
                             cudaFuncAttributeMaxDynamicSharedMemorySize, TSMEM);
        cudaFuncSetAttribute(cam_tc_kernel,
                             cudaFuncAttributeMaxDynamicSharedMemorySize, CAM_SMEM);
        inited = 1;
    }
    static cudaStream_t s1 = [](){ cudaStream_t s;
        cudaStreamCreateWithFlags(&s, cudaStreamNonBlocking); return s; }();
    static cudaStream_t s2 = [](){ cudaStream_t s;
        cudaStreamCreateWithFlags(&s, cudaStreamNonBlocking); return s; }();
    static cudaEvent_t evF = [](){ cudaEvent_t e;
        cudaEventCreateWithFlags(&e, cudaEventDisableTiming); return e; }();
    static cudaEvent_t evK = [](){ cudaEvent_t e;
        cudaEventCreateWithFlags(&e, cudaEventDisableTiming); return e; }();
    static cudaEvent_t evV = [](){ cudaEvent_t e;
        cudaEventCreateWithFlags(&e, cudaEventDisableTiming); return e; }();
    static cudaEvent_t evJ = [](){ cudaEvent_t e;
        cudaEventCreateWithFlags(&e, cudaEventDisableTiming); return e; }();

    const long CHW = (long)CCH * HW;          // 262144
    const long QHW = (long)C8 * HW;           // 32768
    const long GST = (long)VV * CCH;          // 262144
    cudaStream_t s0 = 0;

    // ---- fork: s1 gets Wk+Wv, s2 gets graph chain ----
    cudaEventRecord(evF, s0);
    cudaStreamWaitEvent(s1, evF, 0);
    cudaStreamWaitEvent(s2, evF, 0);

    // ---------------- PAM ----------------
    launch_gemm(0, 0, Wq, x, q, C8,  HW, CCH, 0, CHW, QHW, BSZ, bq, nullptr, 0, 1.f, nullptr, s0);
    launch_gemm(0, 0, Wk, x, k, C8,  HW, CCH, 0, CHW, QHW, BSZ, bk, nullptr, 0, 1.f, nullptr, s1);
    cudaEventRecord(evK, s1);
    launch_gemm(0, 0, Wv, x, v, CCH, HW, CCH, 0, CHW, CHW, BSZ, bv, nullptr, 0, 1.f, nullptr, s1);
    cudaEventRecord(evV, s1);

    cudaStreamWaitEvent(s0, evK, 0);
    launch_gemm(1, 0, q, k, att1, HW, HW, C8, QHW, QHW, (long)HW * HW, BSZ,
                nullptr, nullptr, 0, 1.f, nullptr, s0);
    softmax_kernel<<<BSZ * HW, 128, 0, s0>>>(att1, HW);
    cudaStreamWaitEvent(s0, evV, 0);
    launch_gemm(0, 1, v, att1, y1, CCH, HW, HW, CHW, (long)HW * HW, CHW, BSZ,
                nullptr, x, CHW, 0.f, gpam, s0);

    // ---------------- CAM (s0, tensor-core flash) ----------------
    {
        dim3 grid(CCH / 128, BSZ);
        cam_tc_kernel<<<grid, 256, CAM_SMEM, s0>>>(y1, gcam, out);
    }

    // ------------- Graph layers (s2) -------------
    const float* inp = vfeat;
    for (int i = 0; i < GNUM; i++) {
        float* outg = (i == GNUM - 1) ? (out + (long)BSZ * CCH * HW) : gbuf;
        launch_gemm(0, 1, inp, Wg + (long)i * CCH * CCH, h,
                    NV * VV, CCH, CCH, 0, 0, 0, 1, nullptr, nullptr, 0, 1.f, nullptr, s2);
        launch_gemm(0, 1, inp, inp, ip, VV, VV, CCH, GST, GST, (long)VV * VV, NV,
                    nullptr, nullptr, 0, 1.f, nullptr, s2);
        graph_build<<<dim3(VV, NV), VV, 0, s2>>>(ip, adj, graph);
        launch_gemm(0, 0, graph, h, hp, VV, CCH, VV, (long)VV * VV, GST, GST, NV,
                    nullptr, nullptr, 0, 1.f, nullptr, s2);
        bn_stats<<<CCH / 32, 256, 0, s2>>>(hp, mean, var, NV * VV, CCH);
        bn_apply<<<(NV * VV * CCH + 255) / 256, 256, 0, s2>>>(
            inp, hp, mean, var, bnw + (long)i * CCH, bnb + (long)i * CCH,
            gg + i, outg, NV * VV * CCH, CCH);
        inp = outg;
    }

    // ---- join ----
    cudaEventRecord(evJ, s2);
    cudaStreamWaitEvent(s0, evJ, 0);
}